// round 9
// baseline (speedup 1.0000x reference)
#include <cuda_runtime.h>
#include <cuda_fp16.h>

typedef unsigned long long u64;
typedef unsigned int u32;

#define NMAX 100000
#define NPAD (NMAX + 128)
#define EMAX 1600000
#define NG   64
#define GTM  128   // rows per GEMM CTA

// ---- device scratch ----
__device__ __half g_ga[NPAD * 64];    // g buffers (double-buffered), fp16
__device__ __half g_gb[NPAD * 64];
__device__ __half g_hbf[NPAD * 64];   // activations fp16 (zero beyond n, never written there)
__device__ float  g_psum[NG * 64];    // pooled partial sums
__device__ float  g_dinv[NMAX];
__device__ int    g_cnt[NMAX];
__device__ int    g_rowptr[NMAX + 1];
__device__ int    g_cursor[NMAX];
__device__ int    g_col[EMAX];
__device__ int    g_incl[128];        // lookback inclusive prefixes (sentinel -1)
__device__ int    g_gstart[NG];
__device__ int    g_gend[NG];

// ---------------- setup kernels ----------------

__global__ void init_k(int n, int nb) {
    int i = blockIdx.x * blockDim.x + threadIdx.x;
    if (i < n) g_cnt[i] = 0;
    if (i < NG) { g_gstart[i] = 0x7fffffff; g_gend[i] = -1; }
    if (i < NG * 64) g_psum[i] = 0.f;
    if (i < 128) g_incl[i] = -1;
}

// x (fp32) -> g_hbf (fp16)
__global__ void xcvt_k(const float* __restrict__ x, int n64) {
    int i = blockIdx.x * blockDim.x + threadIdx.x;   // 8 elems per thread
    if (i * 8 >= n64) return;
    const float4* xp = (const float4*)(x) + i * 2;
    float4 a = xp[0], b = xp[1];
    __half2 h0 = __floats2half2_rn(a.x, a.y);
    __half2 h1 = __floats2half2_rn(a.z, a.w);
    __half2 h2 = __floats2half2_rn(b.x, b.y);
    __half2 h3 = __floats2half2_rn(b.z, b.w);
    ((uint4*)g_hbf)[i] = make_uint4(*(u32*)&h0, *(u32*)&h1, *(u32*)&h2, *(u32*)&h3);
}

// degree count + graph bounds via sorted-batch boundary detection
__global__ void countb_k(const int* __restrict__ dst, const int* __restrict__ batch,
                         int e, int n) {
    int i = blockIdx.x * blockDim.x + threadIdx.x;
    if (i < e) atomicAdd(&g_cnt[dst[i]], 1);
    if (i < n) {
        int b = batch[i];
        if (i == 0) g_gstart[b] = 0;
        else {
            int pb = batch[i - 1];
            if (pb != b) { g_gstart[b] = i; g_gend[pb] = i - 1; }
        }
        if (i == n - 1) g_gend[b] = n - 1;
    }
}

// single-pass scan: block-local scan + decoupled lookback (all blocks resident).
// writes rowptr, cursor, dinv; rowptr[n] = etot.
__global__ void scanf_k(int n, int etot, int nb) {
    int t = threadIdx.x;
    int bid = blockIdx.x;
    int i = bid * 1024 + t;
    int v = (i < n) ? g_cnt[i] : 0;
    if (i < n) g_dinv[i] = rsqrtf((float)v + 1.0f);

    int x = v;
    #pragma unroll
    for (int o = 1; o < 32; o <<= 1) {
        int y = __shfl_up_sync(0xffffffffu, x, o);
        if ((t & 31) >= o) x += y;
    }
    __shared__ int wsum[32];
    __shared__ int s_prev;
    if ((t & 31) == 31) wsum[t >> 5] = x;
    __syncthreads();
    if (t < 32) {
        int y = wsum[t];
        int z = y;
        #pragma unroll
        for (int o = 1; o < 32; o <<= 1) {
            int w = __shfl_up_sync(0xffffffffu, z, o);
            if (t >= o) z += w;
        }
        wsum[t] = z - y;           // exclusive warp offset
        if (t == 31) {
            int total = z;          // block total
            int prev = 0;
            if (bid > 0) {
                // spin for predecessor's inclusive prefix (all blocks resident)
                int p;
                do { p = atomicAdd(&g_incl[bid - 1], 0); } while (p < 0);
                prev = p;
            }
            atomicExch(&g_incl[bid], prev + total);
            s_prev = prev;
        }
    }
    __syncthreads();
    int excl = (x - v) + wsum[t >> 5] + s_prev;
    if (i < n) {
        g_rowptr[i] = excl;
        g_cursor[i] = excl;
    }
    if (i == 0) g_rowptr[n] = etot;
}

__global__ void fill_k(const int* __restrict__ src, const int* __restrict__ dst, int e) {
    int i = blockIdx.x * blockDim.x + threadIdx.x;
    if (i < e) {
        int d = dst[i];
        int p = atomicAdd(&g_cursor[d], 1);
        g_col[p] = src[i];
    }
}

// ---- shared gather: fp32 edge-sum of g rows (R7-proven scalar index loads) ----
static __device__ __forceinline__ float2 gather_sum(const __half2* __restrict__ g2,
                                                    int node, int lane) {
    int beg = g_rowptr[node];
    int end = g_rowptr[node + 1];
    float2 acc = __half22float2(g2[(size_t)node * 32 + lane]);   // self term
    int e = beg;
    for (; e + 8 <= end; e += 8) {
        int s0 = __ldg(&g_col[e + 0]);
        int s1 = __ldg(&g_col[e + 1]);
        int s2 = __ldg(&g_col[e + 2]);
        int s3 = __ldg(&g_col[e + 3]);
        int s4 = __ldg(&g_col[e + 4]);
        int s5 = __ldg(&g_col[e + 5]);
        int s6 = __ldg(&g_col[e + 6]);
        int s7 = __ldg(&g_col[e + 7]);
        float2 f0 = __half22float2(g2[(size_t)s0 * 32 + lane]);
        float2 f1 = __half22float2(g2[(size_t)s1 * 32 + lane]);
        float2 f2 = __half22float2(g2[(size_t)s2 * 32 + lane]);
        float2 f3 = __half22float2(g2[(size_t)s3 * 32 + lane]);
        float2 f4 = __half22float2(g2[(size_t)s4 * 32 + lane]);
        float2 f5 = __half22float2(g2[(size_t)s5 * 32 + lane]);
        float2 f6 = __half22float2(g2[(size_t)s6 * 32 + lane]);
        float2 f7 = __half22float2(g2[(size_t)s7 * 32 + lane]);
        acc.x += ((f0.x + f1.x) + (f2.x + f3.x)) + ((f4.x + f5.x) + (f6.x + f7.x));
        acc.y += ((f0.y + f1.y) + (f2.y + f3.y)) + ((f4.y + f5.y) + (f6.y + f7.y));
    }
    for (; e < end; e++) {
        int s = __ldg(&g_col[e]);
        float2 v = __half22float2(g2[(size_t)s * 32 + lane]);
        acc.x += v.x; acc.y += v.y;
    }
    return acc;
}

// ---------------- HFMA2 GEMM (R5/R7-proven) ----------------
// CTA: 128 rows x 64 cols, 128 threads; thread: 8 rows x 8 cols.
// gout[r] = fp16( dinv[r] * (g_hbf[r] @ W) )
__global__ void __launch_bounds__(128, 4) gemm_h2_k(const float* __restrict__ W,
                                                    __half* __restrict__ gout, int n) {
    __shared__ __align__(16) unsigned char sXT[16384];   // 64 k x 128 halves (swizzled)
    __shared__ __align__(16) __half sWh[4096];           // w[k][c]
    __shared__ float sdinv[GTM];

    int t = threadIdx.x;
    int tile0 = blockIdx.x * GTM;

    {
        const float4* W4 = (const float4*)W;
        __half2* wh2 = (__half2*)sWh;
        #pragma unroll
        for (int j = t; j < 1024; j += 128) {
            float4 v = W4[j];
            wh2[2 * j]     = __floats2half2_rn(v.x, v.y);
            wh2[2 * j + 1] = __floats2half2_rn(v.z, v.w);
        }
    }
    if (t < GTM) {
        int r = tile0 + t;
        sdinv[t] = (r < n) ? g_dinv[r] : 0.f;
    }
    {
        int r = t;
        const uint4* hp = (const uint4*)(g_hbf + (size_t)(tile0 + r) * 64);
        int rc = r >> 3, rb = (r & 7) * 2;
        #pragma unroll
        for (int q = 0; q < 8; q++) {
            uint4 v = hp[q];
            __half h[8];
            *(uint4*)h = v;
            #pragma unroll
            for (int j = 0; j < 8; j++) {
                int k = 8 * q + j;
                *(__half*)(sXT + k * 256 + ((rc ^ (k & 15)) << 4) + rb) = h[j];
            }
        }
    }
    __syncthreads();

    int rg = t & 15;
    int cgp = t >> 4;

    float fac[64];
    #pragma unroll
    for (int a = 0; a < 64; a++) fac[a] = 0.f;

    #pragma unroll
    for (int half = 0; half < 2; half++) {
        __half2 acc[32];
        #pragma unroll
        for (int a = 0; a < 32; a++) acc[a] = __floats2half2_rn(0.f, 0.f);

        #pragma unroll 8
        for (int kk = 0; kk < 32; kk++) {
            int k = half * 32 + kk;
            uint4 xv = *(const uint4*)(sXT + k * 256 + ((rg ^ (k & 15)) << 4));
            uint4 wv = *(const uint4*)(sWh + (size_t)k * 64 + cgp * 8);
            __half2 w0 = *(__half2*)&wv.x, w1 = *(__half2*)&wv.y;
            __half2 w2 = *(__half2*)&wv.z, w3 = *(__half2*)&wv.w;
            u32 xw[4] = {xv.x, xv.y, xv.z, xv.w};
            #pragma unroll
            for (int p = 0; p < 4; p++) {
                __half2 xpair = *(__half2*)&xw[p];
                __half2 xlo = __low2half2(xpair);
                __half2 xhi = __high2half2(xpair);
                acc[(2 * p) * 4 + 0] = __hfma2(xlo, w0, acc[(2 * p) * 4 + 0]);
                acc[(2 * p) * 4 + 1] = __hfma2(xlo, w1, acc[(2 * p) * 4 + 1]);
                acc[(2 * p) * 4 + 2] = __hfma2(xlo, w2, acc[(2 * p) * 4 + 2]);
                acc[(2 * p) * 4 + 3] = __hfma2(xlo, w3, acc[(2 * p) * 4 + 3]);
                acc[(2 * p + 1) * 4 + 0] = __hfma2(xhi, w0, acc[(2 * p + 1) * 4 + 0]);
                acc[(2 * p + 1) * 4 + 1] = __hfma2(xhi, w1, acc[(2 * p + 1) * 4 + 1]);
                acc[(2 * p + 1) * 4 + 2] = __hfma2(xhi, w2, acc[(2 * p + 1) * 4 + 2]);
                acc[(2 * p + 1) * 4 + 3] = __hfma2(xhi, w3, acc[(2 * p + 1) * 4 + 3]);
            }
        }
        #pragma unroll
        for (int j = 0; j < 8; j++)
            #pragma unroll
            for (int cp = 0; cp < 4; cp++) {
                float2 f = __half22float2(acc[j * 4 + cp]);
                fac[j * 8 + 2 * cp]     += f.x;
                fac[j * 8 + 2 * cp + 1] += f.y;
            }
    }

    #pragma unroll
    for (int j = 0; j < 8; j++) {
        int r = 8 * rg + j;
        int node = tile0 + r;
        if (node < n) {
            float di = sdinv[r];
            __half2 o[4];
            #pragma unroll
            for (int cp = 0; cp < 4; cp++)
                o[cp] = __floats2half2_rn(fac[j * 8 + 2 * cp] * di,
                                          fac[j * 8 + 2 * cp + 1] * di);
            ((uint4*)(gout + (size_t)node * 64))[cgp] = *(uint4*)o;
        }
    }
}

// ---------------- aggregation (one warp per node) ----------------
__global__ void __launch_bounds__(256) agg64_k(const float* __restrict__ bias,
                                               const __half* __restrict__ gin, int n) {
    int node = (blockIdx.x * blockDim.x + threadIdx.x) >> 5;
    int lane = threadIdx.x & 31;
    if (node >= n) return;

    float2 acc = gather_sum((const __half2*)gin, node, lane);
    float di = g_dinv[node];
    float2 b = ((const float2*)bias)[lane];
    float ox = fmaxf(di * acc.x + b.x, 0.f);
    float oy = fmaxf(di * acc.y + b.y, 0.f);
    __half2 o2 = __floats2half2_rn(ox, oy);
    ((__half2*)g_hbf)[(size_t)node * 32 + lane] = o2;
}

// ---------------- fused agg (layer 3) + pool partial sums ----------------
__global__ void __launch_bounds__(256) aggpool_k(const float* __restrict__ bias,
                                                 const int* __restrict__ batch,
                                                 const __half* __restrict__ gin, int n) {
    int t = threadIdx.x;
    int w = t >> 5, lane = t & 31;
    int base = (blockIdx.x * 8 + w) * 8;
    float2 b = ((const float2*)bias)[lane];
    const __half2* g2 = (const __half2*)gin;

    float2 ps = make_float2(0.f, 0.f);
    int curg = -1;
    #pragma unroll 1
    for (int i = 0; i < 8; i++) {
        int node = base + i;
        if (node >= n) break;
        float2 acc = gather_sum(g2, node, lane);
        float di = g_dinv[node];
        float ox = di * acc.x + b.x;
        float oy = di * acc.y + b.y;
        int bg = batch[node];
        if (bg != curg) {
            if (curg >= 0) {
                atomicAdd(&g_psum[curg * 64 + 2 * lane], ps.x);
                atomicAdd(&g_psum[curg * 64 + 2 * lane + 1], ps.y);
            }
            ps = make_float2(0.f, 0.f);
            curg = bg;
        }
        ps.x += ox; ps.y += oy;
    }
    if (curg >= 0) {
        atomicAdd(&g_psum[curg * 64 + 2 * lane], ps.x);
        atomicAdd(&g_psum[curg * 64 + 2 * lane + 1], ps.y);
    }
}

// ---------------- final head ----------------
__global__ void final_k(const float* __restrict__ Wl, const float* __restrict__ bl,
                        float* __restrict__ out) {
    int t = threadIdx.x;          // 128 threads = 64 graphs x 2 classes
    int g = t >> 1, c = t & 1;
    float s = 0.f;
    #pragma unroll
    for (int k = 0; k < 64; k++) s += g_psum[g * 64 + k] * Wl[k * 2 + c];
    int st = g_gstart[g], en = g_gend[g];
    float cntf = (en >= st) ? (float)(en - st + 1) : 0.f;
    out[t] = s / fmaxf(cntf, 1.f) + bl[c];
}

// ---------------- launch ----------------

extern "C" void kernel_launch(void* const* d_in, const int* in_sizes, int n_in,
                              void* d_out, int out_size) {
    const float* x     = (const float*)d_in[0];
    const int*   ei    = (const int*)d_in[1];
    const int*   batch = (const int*)d_in[2];
    const float* W1 = (const float*)d_in[3]; const float* b1 = (const float*)d_in[4];
    const float* W2 = (const float*)d_in[5]; const float* b2 = (const float*)d_in[6];
    const float* W3 = (const float*)d_in[7]; const float* b3 = (const float*)d_in[8];
    const float* Wl = (const float*)d_in[9]; const float* bl = (const float*)d_in[10];

    int n = in_sizes[0] / 64;
    int e = in_sizes[1] / 2;
    const int* src = ei;
    const int* dst = ei + e;

    int nb = (n + 1023) / 1024;
    int me = (e > n) ? e : n;
    int ntile = (n + GTM - 1) / GTM;

    __half *ga, *gb;
    cudaGetSymbolAddress((void**)&ga, g_ga);
    cudaGetSymbolAddress((void**)&gb, g_gb);

    cudaStream_t sB;
    cudaStreamCreateWithFlags(&sB, cudaStreamNonBlocking);
    cudaEvent_t e0, eD, eF;
    cudaEventCreateWithFlags(&e0, cudaEventDisableTiming);
    cudaEventCreateWithFlags(&eD, cudaEventDisableTiming);
    cudaEventCreateWithFlags(&eF, cudaEventDisableTiming);

    // fork
    cudaEventRecord(e0, 0);
    cudaStreamWaitEvent(sB, e0, 0);

    // stream 0: x -> fp16 (overlaps CSR build)
    xcvt_k<<<(n * 8 + 255) / 256, 256>>>(x, n * 64);

    // stream B: CSR build
    init_k  <<<(n + 255) / 256, 256, 0, sB>>>(n, nb);
    countb_k<<<(me + 255) / 256, 256, 0, sB>>>(dst, batch, e, n);
    scanf_k <<<nb, 1024, 0, sB>>>(n, e, nb);
    cudaEventRecord(eD, sB);                       // dinv ready
    fill_k  <<<(e + 255) / 256, 256, 0, sB>>>(src, dst, e);
    cudaEventRecord(eF, sB);                       // CSR ready

    // stream 0: gemm1 (needs dinv + g_hbf) overlaps fill
    cudaStreamWaitEvent(0, eD, 0);
    gemm_h2_k<<<ntile, 128>>>(W1, ga, n);

    // layers (sequential, minimal launches)
    cudaStreamWaitEvent(0, eF, 0);
    agg64_k  <<<(n + 7) / 8, 256>>>(b1, ga, n);
    gemm_h2_k<<<ntile, 128>>>(W2, gb, n);
    agg64_k  <<<(n + 7) / 8, 256>>>(b2, gb, n);
    gemm_h2_k<<<ntile, 128>>>(W3, ga, n);
    aggpool_k<<<(n + 63) / 64, 256>>>(b3, batch, ga, n);
    final_k  <<<1, 128>>>(Wl, bl, (float*)d_out);
}

// round 10
// speedup vs baseline: 1.1584x; 1.1584x over previous
#include <cuda_runtime.h>
#include <cuda_fp16.h>

typedef unsigned long long u64;
typedef unsigned int u32;

#define NMAX 100000
#define NPAD (NMAX + 128)
#define EMAX 1600000
#define NG   64
#define GTM  128   // rows per GEMM CTA

// ---- device scratch ----
__device__ __half g_ga[NPAD * 64];    // g buffers (double-buffered), fp16
__device__ __half g_gb[NPAD * 64];
__device__ __half g_hbf[NPAD * 64];   // activations fp16 (zero beyond n, never written there)
__device__ float  g_psum[NG * 64];    // pooled partial sums
__device__ float  g_dinv[NMAX];
__device__ int    g_cnt[NMAX];
__device__ int    g_rowptr[NMAX + 1];
__device__ int    g_cursor[NMAX];
__device__ int    g_col[EMAX];
__device__ int    g_stat[128];        // lookback status: 0=invalid, (1<<24)|agg, (2<<24)|incl
__device__ int    g_gstart[NG];
__device__ int    g_gend[NG];

// ---------------- setup kernels ----------------

// x (fp32) -> g_hbf (fp16)
__global__ void xcvt_k(const float* __restrict__ x, int n64) {
    int i = blockIdx.x * blockDim.x + threadIdx.x;   // 8 elems per thread
    if (i * 8 >= n64) return;
    const float4* xp = (const float4*)(x) + i * 2;
    float4 a = xp[0], b = xp[1];
    __half2 h0 = __floats2half2_rn(a.x, a.y);
    __half2 h1 = __floats2half2_rn(a.z, a.w);
    __half2 h2 = __floats2half2_rn(b.x, b.y);
    __half2 h3 = __floats2half2_rn(b.z, b.w);
    ((uint4*)g_hbf)[i] = make_uint4(*(u32*)&h0, *(u32*)&h1, *(u32*)&h2, *(u32*)&h3);
}

// degree count + graph bounds + scratch re-init (g_cnt arrives zeroed: scan resets it)
__global__ void countb_k(const int* __restrict__ dst, const int* __restrict__ batch,
                         int e, int n) {
    int i = blockIdx.x * blockDim.x + threadIdx.x;
    if (i < NG * 64) g_psum[i] = 0.f;
    if (i < 128) g_stat[i] = 0;
    if (i < e) atomicAdd(&g_cnt[dst[i]], 1);
    if (i < n) {
        int b = batch[i];
        if (i == 0) g_gstart[b] = 0;
        else {
            int pb = batch[i - 1];
            if (pb != b) { g_gstart[b] = i; g_gend[pb] = i - 1; }
        }
        if (i == n - 1) g_gend[b] = n - 1;
    }
}

// single-pass scan, CUB-style decoupled lookback (warp-parallel, 32 preds/step).
// writes rowptr/cursor/dinv; zeroes g_cnt after reading (self-reset for replay).
__global__ void scan_k(int n, int etot) {
    int t = threadIdx.x;
    int bid = blockIdx.x;
    int i = bid * 1024 + t;
    int v = 0;
    if (i < n) {
        v = g_cnt[i];
        g_dinv[i] = rsqrtf((float)v + 1.0f);
        g_cnt[i] = 0;                      // reset for next replay
    }

    // block-local scan
    int x = v;
    #pragma unroll
    for (int o = 1; o < 32; o <<= 1) {
        int y = __shfl_up_sync(0xffffffffu, x, o);
        if ((t & 31) >= o) x += y;
    }
    __shared__ int wsum[32];
    __shared__ int s_prev;
    if ((t & 31) == 31) wsum[t >> 5] = x;
    __syncthreads();
    if (t < 32) {
        int y = wsum[t];
        int z = y;
        #pragma unroll
        for (int o = 1; o < 32; o <<= 1) {
            int w = __shfl_up_sync(0xffffffffu, z, o);
            if (t >= o) z += w;
        }
        wsum[t] = z - y;                   // exclusive warp offset
        int total = __shfl_sync(0xffffffffu, z, 31);   // block aggregate

        if (bid == 0) {
            if (t == 31) atomicExch(&g_stat[0], (2 << 24) | total);
            if (t == 0)  s_prev = 0;
        } else {
            // publish aggregate immediately (no waiting)
            if (t == 31) atomicExch(&g_stat[bid], (1 << 24) | total);
            // warp-parallel lookback: window of 32 predecessors per step
            int prev = 0;
            int off = 1;
            while (true) {
                int idx = bid - off - t;
                int st;
                if (idx >= 0) {
                    do { st = atomicAdd(&g_stat[idx], 0); } while ((st >> 24) == 0);
                } else {
                    st = 2 << 24;          // virtual INC of value 0
                }
                u32 incmask = __ballot_sync(0xffffffffu, (st >> 24) == 2);
                int val = st & 0xffffff;
                if (incmask) {
                    int firstinc = __ffs(incmask) - 1;     // closest INC to bid
                    int contrib = (t <= firstinc) ? val : 0;
                    #pragma unroll
                    for (int o = 16; o; o >>= 1)
                        contrib += __shfl_xor_sync(0xffffffffu, contrib, o);
                    prev += contrib;
                    break;
                } else {
                    int contrib = val;                     // all 32 are AGG
                    #pragma unroll
                    for (int o = 16; o; o >>= 1)
                        contrib += __shfl_xor_sync(0xffffffffu, contrib, o);
                    prev += contrib;
                    off += 32;
                }
            }
            if (t == 0) {
                atomicExch(&g_stat[bid], (2 << 24) | (prev + total));
                s_prev = prev;
            }
        }
    }
    __syncthreads();
    int excl = (x - v) + wsum[t >> 5] + s_prev;
    if (i < n) {
        g_rowptr[i] = excl;
        g_cursor[i] = excl;
    }
    if (i == 0) g_rowptr[n] = etot;
}

__global__ void fill_k(const int* __restrict__ src, const int* __restrict__ dst, int e) {
    int i = blockIdx.x * blockDim.x + threadIdx.x;
    if (i < e) {
        int d = dst[i];
        int p = atomicAdd(&g_cursor[d], 1);
        g_col[p] = src[i];
    }
}

// ---- shared gather: fp32 edge-sum of g rows (R7-proven scalar index loads) ----
static __device__ __forceinline__ float2 gather_sum(const __half2* __restrict__ g2,
                                                    int node, int lane) {
    int beg = g_rowptr[node];
    int end = g_rowptr[node + 1];
    float2 acc = __half22float2(g2[(size_t)node * 32 + lane]);   // self term
    int e = beg;
    for (; e + 8 <= end; e += 8) {
        int s0 = __ldg(&g_col[e + 0]);
        int s1 = __ldg(&g_col[e + 1]);
        int s2 = __ldg(&g_col[e + 2]);
        int s3 = __ldg(&g_col[e + 3]);
        int s4 = __ldg(&g_col[e + 4]);
        int s5 = __ldg(&g_col[e + 5]);
        int s6 = __ldg(&g_col[e + 6]);
        int s7 = __ldg(&g_col[e + 7]);
        float2 f0 = __half22float2(g2[(size_t)s0 * 32 + lane]);
        float2 f1 = __half22float2(g2[(size_t)s1 * 32 + lane]);
        float2 f2 = __half22float2(g2[(size_t)s2 * 32 + lane]);
        float2 f3 = __half22float2(g2[(size_t)s3 * 32 + lane]);
        float2 f4 = __half22float2(g2[(size_t)s4 * 32 + lane]);
        float2 f5 = __half22float2(g2[(size_t)s5 * 32 + lane]);
        float2 f6 = __half22float2(g2[(size_t)s6 * 32 + lane]);
        float2 f7 = __half22float2(g2[(size_t)s7 * 32 + lane]);
        acc.x += ((f0.x + f1.x) + (f2.x + f3.x)) + ((f4.x + f5.x) + (f6.x + f7.x));
        acc.y += ((f0.y + f1.y) + (f2.y + f3.y)) + ((f4.y + f5.y) + (f6.y + f7.y));
    }
    for (; e < end; e++) {
        int s = __ldg(&g_col[e]);
        float2 v = __half22float2(g2[(size_t)s * 32 + lane]);
        acc.x += v.x; acc.y += v.y;
    }
    return acc;
}

// ---------------- HFMA2 GEMM (R5/R7-proven) ----------------
// CTA: 128 rows x 64 cols, 128 threads; thread: 8 rows x 8 cols.
// gout[r] = fp16( dinv[r] * (g_hbf[r] @ W) ); tiles offset by tileoff.
__global__ void __launch_bounds__(128, 4) gemm_h2_k(const float* __restrict__ W,
                                                    __half* __restrict__ gout,
                                                    int tileoff, int n) {
    __shared__ __align__(16) unsigned char sXT[16384];   // 64 k x 128 halves (swizzled)
    __shared__ __align__(16) __half sWh[4096];           // w[k][c]
    __shared__ float sdinv[GTM];

    int t = threadIdx.x;
    int tile0 = (blockIdx.x + tileoff) * GTM;

    {
        const float4* W4 = (const float4*)W;
        __half2* wh2 = (__half2*)sWh;
        #pragma unroll
        for (int j = t; j < 1024; j += 128) {
            float4 v = W4[j];
            wh2[2 * j]     = __floats2half2_rn(v.x, v.y);
            wh2[2 * j + 1] = __floats2half2_rn(v.z, v.w);
        }
    }
    if (t < GTM) {
        int r = tile0 + t;
        sdinv[t] = (r < n) ? g_dinv[r] : 0.f;
    }
    {
        int r = t;
        const uint4* hp = (const uint4*)(g_hbf + (size_t)(tile0 + r) * 64);
        int rc = r >> 3, rb = (r & 7) * 2;
        #pragma unroll
        for (int q = 0; q < 8; q++) {
            uint4 v = hp[q];
            __half h[8];
            *(uint4*)h = v;
            #pragma unroll
            for (int j = 0; j < 8; j++) {
                int k = 8 * q + j;
                *(__half*)(sXT + k * 256 + ((rc ^ (k & 15)) << 4) + rb) = h[j];
            }
        }
    }
    __syncthreads();

    int rg = t & 15;
    int cgp = t >> 4;

    float fac[64];
    #pragma unroll
    for (int a = 0; a < 64; a++) fac[a] = 0.f;

    #pragma unroll
    for (int half = 0; half < 2; half++) {
        __half2 acc[32];
        #pragma unroll
        for (int a = 0; a < 32; a++) acc[a] = __floats2half2_rn(0.f, 0.f);

        #pragma unroll 8
        for (int kk = 0; kk < 32; kk++) {
            int k = half * 32 + kk;
            uint4 xv = *(const uint4*)(sXT + k * 256 + ((rg ^ (k & 15)) << 4));
            uint4 wv = *(const uint4*)(sWh + (size_t)k * 64 + cgp * 8);
            __half2 w0 = *(__half2*)&wv.x, w1 = *(__half2*)&wv.y;
            __half2 w2 = *(__half2*)&wv.z, w3 = *(__half2*)&wv.w;
            u32 xw[4] = {xv.x, xv.y, xv.z, xv.w};
            #pragma unroll
            for (int p = 0; p < 4; p++) {
                __half2 xpair = *(__half2*)&xw[p];
                __half2 xlo = __low2half2(xpair);
                __half2 xhi = __high2half2(xpair);
                acc[(2 * p) * 4 + 0] = __hfma2(xlo, w0, acc[(2 * p) * 4 + 0]);
                acc[(2 * p) * 4 + 1] = __hfma2(xlo, w1, acc[(2 * p) * 4 + 1]);
                acc[(2 * p) * 4 + 2] = __hfma2(xlo, w2, acc[(2 * p) * 4 + 2]);
                acc[(2 * p) * 4 + 3] = __hfma2(xlo, w3, acc[(2 * p) * 4 + 3]);
                acc[(2 * p + 1) * 4 + 0] = __hfma2(xhi, w0, acc[(2 * p + 1) * 4 + 0]);
                acc[(2 * p + 1) * 4 + 1] = __hfma2(xhi, w1, acc[(2 * p + 1) * 4 + 1]);
                acc[(2 * p + 1) * 4 + 2] = __hfma2(xhi, w2, acc[(2 * p + 1) * 4 + 2]);
                acc[(2 * p + 1) * 4 + 3] = __hfma2(xhi, w3, acc[(2 * p + 1) * 4 + 3]);
            }
        }
        #pragma unroll
        for (int j = 0; j < 8; j++)
            #pragma unroll
            for (int cp = 0; cp < 4; cp++) {
                float2 f = __half22float2(acc[j * 4 + cp]);
                fac[j * 8 + 2 * cp]     += f.x;
                fac[j * 8 + 2 * cp + 1] += f.y;
            }
    }

    #pragma unroll
    for (int j = 0; j < 8; j++) {
        int r = 8 * rg + j;
        int node = tile0 + r;
        if (node < n) {
            float di = sdinv[r];
            __half2 o[4];
            #pragma unroll
            for (int cp = 0; cp < 4; cp++)
                o[cp] = __floats2half2_rn(fac[j * 8 + 2 * cp] * di,
                                          fac[j * 8 + 2 * cp + 1] * di);
            ((uint4*)(gout + (size_t)node * 64))[cgp] = *(uint4*)o;
        }
    }
}

// ---------------- aggregation (one warp per node) ----------------
__global__ void __launch_bounds__(256) agg64_k(const float* __restrict__ bias,
                                               const __half* __restrict__ gin,
                                               int node0, int cnt, int n) {
    int idx = (blockIdx.x * blockDim.x + threadIdx.x) >> 5;
    int lane = threadIdx.x & 31;
    if (idx >= cnt) return;
    int node = node0 + idx;
    if (node >= n) return;

    float2 acc = gather_sum((const __half2*)gin, node, lane);
    float di = g_dinv[node];
    float2 b = ((const float2*)bias)[lane];
    float ox = fmaxf(di * acc.x + b.x, 0.f);
    float oy = fmaxf(di * acc.y + b.y, 0.f);
    __half2 o2 = __floats2half2_rn(ox, oy);
    ((__half2*)g_hbf)[(size_t)node * 32 + lane] = o2;
}

// ---------------- fused agg (layer 3) + pool partial sums ----------------
__global__ void __launch_bounds__(256) aggpool_k(const float* __restrict__ bias,
                                                 const int* __restrict__ batch,
                                                 const __half* __restrict__ gin, int n) {
    int t = threadIdx.x;
    int w = t >> 5, lane = t & 31;
    int base = (blockIdx.x * 8 + w) * 8;
    float2 b = ((const float2*)bias)[lane];
    const __half2* g2 = (const __half2*)gin;

    float2 ps = make_float2(0.f, 0.f);
    int curg = -1;
    #pragma unroll 1
    for (int i = 0; i < 8; i++) {
        int node = base + i;
        if (node >= n) break;
        float2 acc = gather_sum(g2, node, lane);
        float di = g_dinv[node];
        float ox = di * acc.x + b.x;
        float oy = di * acc.y + b.y;
        int bg = batch[node];
        if (bg != curg) {
            if (curg >= 0) {
                atomicAdd(&g_psum[curg * 64 + 2 * lane], ps.x);
                atomicAdd(&g_psum[curg * 64 + 2 * lane + 1], ps.y);
            }
            ps = make_float2(0.f, 0.f);
            curg = bg;
        }
        ps.x += ox; ps.y += oy;
    }
    if (curg >= 0) {
        atomicAdd(&g_psum[curg * 64 + 2 * lane], ps.x);
        atomicAdd(&g_psum[curg * 64 + 2 * lane + 1], ps.y);
    }
}

// ---------------- final head ----------------
__global__ void final_k(const float* __restrict__ Wl, const float* __restrict__ bl,
                        float* __restrict__ out) {
    int t = threadIdx.x;          // 128 threads = 64 graphs x 2 classes
    int g = t >> 1, c = t & 1;
    float s = 0.f;
    #pragma unroll
    for (int k = 0; k < 64; k++) s += g_psum[g * 64 + k] * Wl[k * 2 + c];
    int st = g_gstart[g], en = g_gend[g];
    float cntf = (en >= st) ? (float)(en - st + 1) : 0.f;
    out[t] = s / fmaxf(cntf, 1.f) + bl[c];
}

// ---------------- launch ----------------

extern "C" void kernel_launch(void* const* d_in, const int* in_sizes, int n_in,
                              void* d_out, int out_size) {
    const float* x     = (const float*)d_in[0];
    const int*   ei    = (const int*)d_in[1];
    const int*   batch = (const int*)d_in[2];
    const float* W1 = (const float*)d_in[3]; const float* b1 = (const float*)d_in[4];
    const float* W2 = (const float*)d_in[5]; const float* b2 = (const float*)d_in[6];
    const float* W3 = (const float*)d_in[7]; const float* b3 = (const float*)d_in[8];
    const float* Wl = (const float*)d_in[9]; const float* bl = (const float*)d_in[10];

    int n = in_sizes[0] / 64;
    int e = in_sizes[1] / 2;
    const int* src = ei;
    const int* dst = ei + e;

    int nb = (n + 1023) / 1024;
    int me = (e > n) ? e : n;
    int ntile = (n + GTM - 1) / GTM;
    int tilesA = (ntile + 1) / 2;
    int tilesB = ntile - tilesA;
    int nh = tilesA * GTM;
    int cntA = (nh < n) ? nh : n;
    int cntB = n - cntA;

    __half *ga, *gb;
    cudaGetSymbolAddress((void**)&ga, g_ga);
    cudaGetSymbolAddress((void**)&gb, g_gb);

    cudaStream_t sB;
    cudaStreamCreateWithFlags(&sB, cudaStreamNonBlocking);
    cudaEvent_t e0, eD, eF, eA1, eG2, eA2, eG3;
    cudaEventCreateWithFlags(&e0,  cudaEventDisableTiming);
    cudaEventCreateWithFlags(&eD,  cudaEventDisableTiming);
    cudaEventCreateWithFlags(&eF,  cudaEventDisableTiming);
    cudaEventCreateWithFlags(&eA1, cudaEventDisableTiming);
    cudaEventCreateWithFlags(&eG2, cudaEventDisableTiming);
    cudaEventCreateWithFlags(&eA2, cudaEventDisableTiming);
    cudaEventCreateWithFlags(&eG3, cudaEventDisableTiming);

    // fork
    cudaEventRecord(e0, 0);
    cudaStreamWaitEvent(sB, e0, 0);

    // stream 0: x -> fp16 (overlaps CSR build)
    xcvt_k<<<(n * 8 + 255) / 256, 256>>>(x, n * 64);

    // stream B: CSR build (countb self-reinits psum/stat; scan self-resets cnt)
    countb_k<<<(me + 255) / 256, 256, 0, sB>>>(dst, batch, e, n);
    scan_k  <<<nb, 1024, 0, sB>>>(n, e);
    cudaEventRecord(eD, sB);                       // dinv ready
    fill_k  <<<(e + 255) / 256, 256, 0, sB>>>(src, dst, e);
    cudaEventRecord(eF, sB);                       // CSR ready

    // stream 0: gemm1 (needs dinv + g_hbf) overlaps fill
    cudaStreamWaitEvent(0, eD, 0);
    gemm_h2_k<<<ntile, 128>>>(W1, ga, 0, n);

    // layer 1 agg, half A
    cudaStreamWaitEvent(0, eF, 0);
    agg64_k<<<(cntA + 7) / 8, 256>>>(b1, ga, 0, cntA, n);
    cudaEventRecord(eA1, 0);

    // sB: gemm2 half A concurrent with agg1b+gemm2b on 0
    cudaStreamWaitEvent(sB, eA1, 0);
    gemm_h2_k<<<tilesA, 128, 0, sB>>>(W2, gb, 0, n);
    cudaEventRecord(eG2, sB);

    // stream 0: agg1 half B, then gemm2 half B
    agg64_k<<<(cntB + 7) / 8, 256>>>(b1, ga, cntA, cntB, n);
    gemm_h2_k<<<tilesB, 128>>>(W2, gb, tilesA, n);

    // layer 2 agg half A
    cudaStreamWaitEvent(0, eG2, 0);
    agg64_k<<<(cntA + 7) / 8, 256>>>(b2, gb, 0, cntA, n);
    cudaEventRecord(eA2, 0);

    // sB: gemm3 half A concurrent with agg2b+gemm3b on 0
    cudaStreamWaitEvent(sB, eA2, 0);
    gemm_h2_k<<<tilesA, 128, 0, sB>>>(W3, ga, 0, n);
    cudaEventRecord(eG3, sB);

    // stream 0: agg2 half B, gemm3 half B
    agg64_k<<<(cntB + 7) / 8, 256>>>(b2, gb, cntA, cntB, n);
    gemm_h2_k<<<tilesB, 128>>>(W3, ga, tilesA, n);

    // layer 3 agg + pool
    cudaStreamWaitEvent(0, eG3, 0);
    aggpool_k<<<(n + 63) / 64, 256>>>(b3, batch, ga, n);
    final_k<<<1, 128>>>(Wl, bl, (float*)d_out);
}

// round 11
// speedup vs baseline: 1.1593x; 1.0008x over previous
#include <cuda_runtime.h>
#include <cuda_fp16.h>

typedef unsigned long long u64;
typedef unsigned int u32;

#define NMAX 100000
#define NPAD (NMAX + 128)
#define EMAX 1600000
#define NG   64
#define GTM  128   // rows per GEMM CTA

// ---- device scratch ----
__device__ __half g_ga[NPAD * 64];    // g buffers (double-buffered), fp16
__device__ __half g_gb[NPAD * 64];
__device__ __half g_hbf[NPAD * 64];   // activations fp16 (zero beyond n, never written there)
__device__ float  g_psum[NG * 64];    // pooled partial sums
__device__ float  g_dinv[NMAX];
__device__ int    g_cnt[NMAX];        // degree counts (self-resetting each replay)
__device__ int    g_rowptr[NMAX + 1];
__device__ int    g_rank[EMAX];       // edge rank within its dst bucket
__device__ int    g_col[EMAX];
__device__ int    g_bsums[1024];
__device__ int    g_gstart[NG];
__device__ int    g_gend[NG];

// ---------------- setup kernels ----------------

// x (fp32) -> g_hbf (fp16)
__global__ void xcvt_k(const float* __restrict__ x, int n64) {
    int i = blockIdx.x * blockDim.x + threadIdx.x;   // 8 elems per thread
    if (i * 8 >= n64) return;
    const float4* xp = (const float4*)(x) + i * 2;
    float4 a = xp[0], b = xp[1];
    __half2 h0 = __floats2half2_rn(a.x, a.y);
    __half2 h1 = __floats2half2_rn(a.z, a.w);
    __half2 h2 = __floats2half2_rn(b.x, b.y);
    __half2 h3 = __floats2half2_rn(b.z, b.w);
    ((uint4*)g_hbf)[i] = make_uint4(*(u32*)&h0, *(u32*)&h1, *(u32*)&h2, *(u32*)&h3);
}

// degree count (+ per-edge rank) + graph bounds + psum re-zero.
// g_cnt arrives zeroed (scan1 resets it after reading each replay).
__global__ void countb_k(const int* __restrict__ dst, const int* __restrict__ batch,
                         int e, int n) {
    int i = blockIdx.x * blockDim.x + threadIdx.x;
    if (i < NG * 64) g_psum[i] = 0.f;
    if (i < e) {
        int p = atomicAdd(&g_cnt[dst[i]], 1);
        g_rank[i] = p;
    }
    if (i < n) {
        int b = batch[i];
        if (i == 0) g_gstart[b] = 0;
        else {
            int pb = batch[i - 1];
            if (pb != b) { g_gstart[b] = i; g_gend[pb] = i - 1; }
        }
        if (i == n - 1) g_gend[b] = n - 1;
    }
}

// 3-kernel scan (R7-proven). scan1 also computes dinv and self-resets g_cnt.
__global__ void scan1_k(int n) {
    int t = threadIdx.x;
    int i = blockIdx.x * 1024 + t;
    int v = 0;
    if (i < n) {
        v = g_cnt[i];
        g_dinv[i] = rsqrtf((float)v + 1.0f);
        g_cnt[i] = 0;                      // reset for next replay
    }
    int x = v;
    #pragma unroll
    for (int o = 1; o < 32; o <<= 1) {
        int y = __shfl_up_sync(0xffffffffu, x, o);
        if ((t & 31) >= o) x += y;
    }
    __shared__ int wsum[32];
    if ((t & 31) == 31) wsum[t >> 5] = x;
    __syncthreads();
    if (t < 32) {
        int y = wsum[t];
        int z = y;
        #pragma unroll
        for (int o = 1; o < 32; o <<= 1) {
            int w = __shfl_up_sync(0xffffffffu, z, o);
            if (t >= o) z += w;
        }
        wsum[t] = z - y;
        if (t == 31) g_bsums[blockIdx.x] = z;
    }
    __syncthreads();
    int excl = (x - v) + wsum[t >> 5];
    if (i < n) g_rowptr[i] = excl;
}

__global__ void scan2_k(int nb) {
    int t = threadIdx.x;
    int v = (t < nb) ? g_bsums[t] : 0;
    int x = v;
    #pragma unroll
    for (int o = 1; o < 32; o <<= 1) {
        int y = __shfl_up_sync(0xffffffffu, x, o);
        if ((t & 31) >= o) x += y;
    }
    __shared__ int wsum[32];
    if ((t & 31) == 31) wsum[t >> 5] = x;
    __syncthreads();
    if (t < 32) {
        int y = wsum[t];
        int z = y;
        #pragma unroll
        for (int o = 1; o < 32; o <<= 1) {
            int w = __shfl_up_sync(0xffffffffu, z, o);
            if (t >= o) z += w;
        }
        wsum[t] = z - y;
    }
    __syncthreads();
    int excl = (x - v) + wsum[t >> 5];
    if (t < nb) g_bsums[t] = excl;
}

__global__ void scan3_k(int n, int etot) {
    int i = blockIdx.x * 1024 + threadIdx.x;
    if (i < n) g_rowptr[i] += g_bsums[blockIdx.x];
    if (i == 0) g_rowptr[n] = etot;
}

// atomic-free fill: position = rowptr[dst] + rank
__global__ void fill_k(const int* __restrict__ src, const int* __restrict__ dst, int e) {
    int i = blockIdx.x * blockDim.x + threadIdx.x;
    if (i < e) {
        int d = dst[i];
        int p = __ldg(&g_rowptr[d]) + g_rank[i];
        g_col[p] = src[i];
    }
}

// ---- shared gather: fp32 edge-sum of g rows (R7-proven scalar index loads) ----
static __device__ __forceinline__ float2 gather_sum(const __half2* __restrict__ g2,
                                                    int node, int lane) {
    int beg = g_rowptr[node];
    int end = g_rowptr[node + 1];
    float2 acc = __half22float2(g2[(size_t)node * 32 + lane]);   // self term
    int e = beg;
    for (; e + 8 <= end; e += 8) {
        int s0 = __ldg(&g_col[e + 0]);
        int s1 = __ldg(&g_col[e + 1]);
        int s2 = __ldg(&g_col[e + 2]);
        int s3 = __ldg(&g_col[e + 3]);
        int s4 = __ldg(&g_col[e + 4]);
        int s5 = __ldg(&g_col[e + 5]);
        int s6 = __ldg(&g_col[e + 6]);
        int s7 = __ldg(&g_col[e + 7]);
        float2 f0 = __half22float2(g2[(size_t)s0 * 32 + lane]);
        float2 f1 = __half22float2(g2[(size_t)s1 * 32 + lane]);
        float2 f2 = __half22float2(g2[(size_t)s2 * 32 + lane]);
        float2 f3 = __half22float2(g2[(size_t)s3 * 32 + lane]);
        float2 f4 = __half22float2(g2[(size_t)s4 * 32 + lane]);
        float2 f5 = __half22float2(g2[(size_t)s5 * 32 + lane]);
        float2 f6 = __half22float2(g2[(size_t)s6 * 32 + lane]);
        float2 f7 = __half22float2(g2[(size_t)s7 * 32 + lane]);
        acc.x += ((f0.x + f1.x) + (f2.x + f3.x)) + ((f4.x + f5.x) + (f6.x + f7.x));
        acc.y += ((f0.y + f1.y) + (f2.y + f3.y)) + ((f4.y + f5.y) + (f6.y + f7.y));
    }
    for (; e < end; e++) {
        int s = __ldg(&g_col[e]);
        float2 v = __half22float2(g2[(size_t)s * 32 + lane]);
        acc.x += v.x; acc.y += v.y;
    }
    return acc;
}

// ---------------- HFMA2 GEMM (R5/R7-proven) ----------------
__global__ void __launch_bounds__(128, 4) gemm_h2_k(const float* __restrict__ W,
                                                    __half* __restrict__ gout,
                                                    int tileoff, int n) {
    __shared__ __align__(16) unsigned char sXT[16384];   // 64 k x 128 halves (swizzled)
    __shared__ __align__(16) __half sWh[4096];           // w[k][c]
    __shared__ float sdinv[GTM];

    int t = threadIdx.x;
    int tile0 = (blockIdx.x + tileoff) * GTM;

    {
        const float4* W4 = (const float4*)W;
        __half2* wh2 = (__half2*)sWh;
        #pragma unroll
        for (int j = t; j < 1024; j += 128) {
            float4 v = W4[j];
            wh2[2 * j]     = __floats2half2_rn(v.x, v.y);
            wh2[2 * j + 1] = __floats2half2_rn(v.z, v.w);
        }
    }
    if (t < GTM) {
        int r = tile0 + t;
        sdinv[t] = (r < n) ? g_dinv[r] : 0.f;
    }
    {
        int r = t;
        const uint4* hp = (const uint4*)(g_hbf + (size_t)(tile0 + r) * 64);
        int rc = r >> 3, rb = (r & 7) * 2;
        #pragma unroll
        for (int q = 0; q < 8; q++) {
            uint4 v = hp[q];
            __half h[8];
            *(uint4*)h = v;
            #pragma unroll
            for (int j = 0; j < 8; j++) {
                int k = 8 * q + j;
                *(__half*)(sXT + k * 256 + ((rc ^ (k & 15)) << 4) + rb) = h[j];
            }
        }
    }
    __syncthreads();

    int rg = t & 15;
    int cgp = t >> 4;

    float fac[64];
    #pragma unroll
    for (int a = 0; a < 64; a++) fac[a] = 0.f;

    #pragma unroll
    for (int half = 0; half < 2; half++) {
        __half2 acc[32];
        #pragma unroll
        for (int a = 0; a < 32; a++) acc[a] = __floats2half2_rn(0.f, 0.f);

        #pragma unroll 8
        for (int kk = 0; kk < 32; kk++) {
            int k = half * 32 + kk;
            uint4 xv = *(const uint4*)(sXT + k * 256 + ((rg ^ (k & 15)) << 4));
            uint4 wv = *(const uint4*)(sWh + (size_t)k * 64 + cgp * 8);
            __half2 w0 = *(__half2*)&wv.x, w1 = *(__half2*)&wv.y;
            __half2 w2 = *(__half2*)&wv.z, w3 = *(__half2*)&wv.w;
            u32 xw[4] = {xv.x, xv.y, xv.z, xv.w};
            #pragma unroll
            for (int p = 0; p < 4; p++) {
                __half2 xpair = *(__half2*)&xw[p];
                __half2 xlo = __low2half2(xpair);
                __half2 xhi = __high2half2(xpair);
                acc[(2 * p) * 4 + 0] = __hfma2(xlo, w0, acc[(2 * p) * 4 + 0]);
                acc[(2 * p) * 4 + 1] = __hfma2(xlo, w1, acc[(2 * p) * 4 + 1]);
                acc[(2 * p) * 4 + 2] = __hfma2(xlo, w2, acc[(2 * p) * 4 + 2]);
                acc[(2 * p) * 4 + 3] = __hfma2(xlo, w3, acc[(2 * p) * 4 + 3]);
                acc[(2 * p + 1) * 4 + 0] = __hfma2(xhi, w0, acc[(2 * p + 1) * 4 + 0]);
                acc[(2 * p + 1) * 4 + 1] = __hfma2(xhi, w1, acc[(2 * p + 1) * 4 + 1]);
                acc[(2 * p + 1) * 4 + 2] = __hfma2(xhi, w2, acc[(2 * p + 1) * 4 + 2]);
                acc[(2 * p + 1) * 4 + 3] = __hfma2(xhi, w3, acc[(2 * p + 1) * 4 + 3]);
            }
        }
        #pragma unroll
        for (int j = 0; j < 8; j++)
            #pragma unroll
            for (int cp = 0; cp < 4; cp++) {
                float2 f = __half22float2(acc[j * 4 + cp]);
                fac[j * 8 + 2 * cp]     += f.x;
                fac[j * 8 + 2 * cp + 1] += f.y;
            }
    }

    #pragma unroll
    for (int j = 0; j < 8; j++) {
        int r = 8 * rg + j;
        int node = tile0 + r;
        if (node < n) {
            float di = sdinv[r];
            __half2 o[4];
            #pragma unroll
            for (int cp = 0; cp < 4; cp++)
                o[cp] = __floats2half2_rn(fac[j * 8 + 2 * cp] * di,
                                          fac[j * 8 + 2 * cp + 1] * di);
            ((uint4*)(gout + (size_t)node * 64))[cgp] = *(uint4*)o;
        }
    }
}

// ---------------- aggregation (one warp per node) ----------------
__global__ void __launch_bounds__(256) agg64_k(const float* __restrict__ bias,
                                               const __half* __restrict__ gin,
                                               int node0, int cnt, int n) {
    int idx = (blockIdx.x * blockDim.x + threadIdx.x) >> 5;
    int lane = threadIdx.x & 31;
    if (idx >= cnt) return;
    int node = node0 + idx;
    if (node >= n) return;

    float2 acc = gather_sum((const __half2*)gin, node, lane);
    float di = g_dinv[node];
    float2 b = ((const float2*)bias)[lane];
    float ox = fmaxf(di * acc.x + b.x, 0.f);
    float oy = fmaxf(di * acc.y + b.y, 0.f);
    __half2 o2 = __floats2half2_rn(ox, oy);
    ((__half2*)g_hbf)[(size_t)node * 32 + lane] = o2;
}

// ---------------- fused agg (layer 3) + pool partial sums ----------------
__global__ void __launch_bounds__(256) aggpool_k(const float* __restrict__ bias,
                                                 const int* __restrict__ batch,
                                                 const __half* __restrict__ gin, int n) {
    int t = threadIdx.x;
    int w = t >> 5, lane = t & 31;
    int base = (blockIdx.x * 8 + w) * 8;
    float2 b = ((const float2*)bias)[lane];
    const __half2* g2 = (const __half2*)gin;

    float2 ps = make_float2(0.f, 0.f);
    int curg = -1;
    #pragma unroll 1
    for (int i = 0; i < 8; i++) {
        int node = base + i;
        if (node >= n) break;
        float2 acc = gather_sum(g2, node, lane);
        float di = g_dinv[node];
        float ox = di * acc.x + b.x;
        float oy = di * acc.y + b.y;
        int bg = batch[node];
        if (bg != curg) {
            if (curg >= 0) {
                atomicAdd(&g_psum[curg * 64 + 2 * lane], ps.x);
                atomicAdd(&g_psum[curg * 64 + 2 * lane + 1], ps.y);
            }
            ps = make_float2(0.f, 0.f);
            curg = bg;
        }
        ps.x += ox; ps.y += oy;
    }
    if (curg >= 0) {
        atomicAdd(&g_psum[curg * 64 + 2 * lane], ps.x);
        atomicAdd(&g_psum[curg * 64 + 2 * lane + 1], ps.y);
    }
}

// ---------------- final head ----------------
__global__ void final_k(const float* __restrict__ Wl, const float* __restrict__ bl,
                        float* __restrict__ out) {
    int t = threadIdx.x;          // 128 threads = 64 graphs x 2 classes
    int g = t >> 1, c = t & 1;
    float s = 0.f;
    #pragma unroll
    for (int k = 0; k < 64; k++) s += g_psum[g * 64 + k] * Wl[k * 2 + c];
    int st = g_gstart[g], en = g_gend[g];
    float cntf = (en >= st) ? (float)(en - st + 1) : 0.f;
    out[t] = s / fmaxf(cntf, 1.f) + bl[c];
}

// ---------------- launch ----------------

extern "C" void kernel_launch(void* const* d_in, const int* in_sizes, int n_in,
                              void* d_out, int out_size) {
    const float* x     = (const float*)d_in[0];
    const int*   ei    = (const int*)d_in[1];
    const int*   batch = (const int*)d_in[2];
    const float* W1 = (const float*)d_in[3]; const float* b1 = (const float*)d_in[4];
    const float* W2 = (const float*)d_in[5]; const float* b2 = (const float*)d_in[6];
    const float* W3 = (const float*)d_in[7]; const float* b3 = (const float*)d_in[8];
    const float* Wl = (const float*)d_in[9]; const float* bl = (const float*)d_in[10];

    int n = in_sizes[0] / 64;
    int e = in_sizes[1] / 2;
    const int* src = ei;
    const int* dst = ei + e;

    int nb = (n + 1023) / 1024;
    int me = (e > n) ? e : n;
    int ntile = (n + GTM - 1) / GTM;
    int tilesA = (ntile + 1) / 2;
    int tilesB = ntile - tilesA;
    int nh = tilesA * GTM;
    int cntA = (nh < n) ? nh : n;
    int cntB = n - cntA;

    __half *ga, *gb;
    cudaGetSymbolAddress((void**)&ga, g_ga);
    cudaGetSymbolAddress((void**)&gb, g_gb);

    cudaStream_t sB;
    cudaStreamCreateWithFlags(&sB, cudaStreamNonBlocking);
    cudaEvent_t e0, eD, eF, eA1, eG2, eA2, eG3;
    cudaEventCreateWithFlags(&e0,  cudaEventDisableTiming);
    cudaEventCreateWithFlags(&eD,  cudaEventDisableTiming);
    cudaEventCreateWithFlags(&eF,  cudaEventDisableTiming);
    cudaEventCreateWithFlags(&eA1, cudaEventDisableTiming);
    cudaEventCreateWithFlags(&eG2, cudaEventDisableTiming);
    cudaEventCreateWithFlags(&eA2, cudaEventDisableTiming);
    cudaEventCreateWithFlags(&eG3, cudaEventDisableTiming);

    // fork
    cudaEventRecord(e0, 0);
    cudaStreamWaitEvent(sB, e0, 0);

    // stream 0: x -> fp16 (overlaps CSR build)
    xcvt_k<<<(n * 8 + 255) / 256, 256>>>(x, n * 64);

    // stream B: CSR build (countb re-zeros psum; scan1 self-resets cnt)
    countb_k<<<(me + 255) / 256, 256, 0, sB>>>(dst, batch, e, n);
    scan1_k <<<nb, 1024, 0, sB>>>(n);
    cudaEventRecord(eD, sB);                       // dinv ready
    scan2_k <<<1, 1024, 0, sB>>>(nb);
    scan3_k <<<nb, 1024, 0, sB>>>(n, e);
    fill_k  <<<(e + 255) / 256, 256, 0, sB>>>(src, dst, e);
    cudaEventRecord(eF, sB);                       // CSR ready

    // stream 0: gemm1 (needs dinv + g_hbf) overlaps scan2/scan3/fill
    cudaStreamWaitEvent(0, eD, 0);
    gemm_h2_k<<<ntile, 128>>>(W1, ga, 0, n);

    // layer 1 agg, half A
    cudaStreamWaitEvent(0, eF, 0);
    agg64_k<<<(cntA + 7) / 8, 256>>>(b1, ga, 0, cntA, n);
    cudaEventRecord(eA1, 0);

    // sB: gemm2 half A concurrent with agg1b+gemm2b on 0
    cudaStreamWaitEvent(sB, eA1, 0);
    gemm_h2_k<<<tilesA, 128, 0, sB>>>(W2, gb, 0, n);
    cudaEventRecord(eG2, sB);

    // stream 0: agg1 half B, then gemm2 half B
    agg64_k<<<(cntB + 7) / 8, 256>>>(b1, ga, cntA, cntB, n);
    gemm_h2_k<<<tilesB, 128>>>(W2, gb, tilesA, n);

    // layer 2 agg half A
    cudaStreamWaitEvent(0, eG2, 0);
    agg64_k<<<(cntA + 7) / 8, 256>>>(b2, gb, 0, cntA, n);
    cudaEventRecord(eA2, 0);

    // sB: gemm3 half A concurrent with agg2b+gemm3b on 0
    cudaStreamWaitEvent(sB, eA2, 0);
    gemm_h2_k<<<tilesA, 128, 0, sB>>>(W3, ga, 0, n);
    cudaEventRecord(eG3, sB);

    // stream 0: agg2 half B, gemm3 half B
    agg64_k<<<(cntB + 7) / 8, 256>>>(b2, gb, cntA, cntB, n);
    gemm_h2_k<<<tilesB, 128>>>(W3, ga, tilesA, n);

    // layer 3 agg + pool
    cudaStreamWaitEvent(0, eG3, 0);
    aggpool_k<<<(n + 63) / 64, 256>>>(b3, batch, ga, n);
    final_k<<<1, 128>>>(Wl, bl, (float*)d_out);
}